// round 5
// baseline (speedup 1.0000x reference)
#include <cuda_runtime.h>
#include <stdint.h>

#define N_MAX 100000
#define E_MAX 6400000

// ---- scratch (device globals: no allocation allowed) ----
__device__ int      g_src[E_MAX];
__device__ int      g_dst[E_MAX];
__device__ unsigned g_deg[N_MAX];
__device__ float    g_dinv[N_MAX];
__device__ float    g_val[N_MAX];   // per-node scalar payload (g1, then g2)
__device__ float    g_agg[N_MAX];   // layer-1 aggregation
__device__ int      g_is64;         // edge_index dtype flag (1 = int64)

// ---------------------------------------------------------------------------
// threefry2x32 — exact JAX schedule: 20 rounds = 5 blocks of 4
// ---------------------------------------------------------------------------
__host__ __device__ __forceinline__ void tf2x32(uint32_t k0, uint32_t k1,
                                                uint32_t x0, uint32_t x1,
                                                uint32_t &o0, uint32_t &o1) {
    const uint32_t ks2 = k0 ^ k1 ^ 0x1BD11BDAu;
#define TF_RND(R) { x0 += x1; x1 = (x1 << (R)) | (x1 >> (32 - (R))); x1 ^= x0; }
    x0 += k0; x1 += k1;
    TF_RND(13) TF_RND(15) TF_RND(26) TF_RND(6)
    x0 += k1;  x1 += ks2 + 1u;
    TF_RND(17) TF_RND(29) TF_RND(16) TF_RND(24)
    x0 += ks2; x1 += k0 + 2u;
    TF_RND(13) TF_RND(15) TF_RND(26) TF_RND(6)
    x0 += k0;  x1 += k1 + 3u;
    TF_RND(17) TF_RND(29) TF_RND(16) TF_RND(24)
    x0 += k1;  x1 += ks2 + 4u;
    TF_RND(13) TF_RND(15) TF_RND(26) TF_RND(6)
    x0 += ks2; x1 += k0 + 5u;
#undef TF_RND
    o0 = x0; o1 = x1;
}

__device__ __forceinline__ bool keep_bit(uint32_t ka, uint32_t kb, uint32_t idx) {
    uint32_t a, b;
    tf2x32(ka, kb, 0u, idx, a, b);
    uint32_t bits = a ^ b;
    float u = __uint_as_float((bits >> 9) | 0x3f800000u) - 1.0f;
    return u < 0.4f;
}

// ---------------------------------------------------------------------------
// kernels
// ---------------------------------------------------------------------------

// zero counters/accumulators/out + dtype detection (block 0)
__global__ void k_init(float* __restrict__ out, const unsigned* __restrict__ e, int N) {
    int n = blockIdx.x * blockDim.x + threadIdx.x;
    if (n < N) { g_deg[n] = 0u; g_agg[n] = 0.0f; out[n] = 0.0f; }
    if (blockIdx.x == 0) {
        __shared__ int any32;
        if (threadIdx.x == 0) any32 = 0;
        __syncthreads();
        int local = 0;
        for (int j = threadIdx.x; j < 4096; j += blockDim.x)
            if (e[2 * j + 1] != 0u) local = 1;
        if (local) any32 = 1;
        __syncthreads();
        if (threadIdx.x == 0) g_is64 = (any32 == 0) ? 1 : 0;
    }
}

// Convert edge_index -> int32 src/dst and count in-degree. 4 edges per thread.
__global__ void __launch_bounds__(256) k_convert(const long long* __restrict__ e, int E) {
    int i = blockIdx.x * blockDim.x + threadIdx.x;   // quad index
    if (i * 4 >= E) return;
    int4 sv, dv;
    if (g_is64) {
        const longlong2* s2 = reinterpret_cast<const longlong2*>(e);
        const longlong2* d2 = reinterpret_cast<const longlong2*>(e + E);
        longlong2 sa = s2[2 * i], sb = s2[2 * i + 1];
        longlong2 da = d2[2 * i], db = d2[2 * i + 1];
        sv = make_int4((int)sa.x, (int)sa.y, (int)sb.x, (int)sb.y);
        dv = make_int4((int)da.x, (int)da.y, (int)db.x, (int)db.y);
    } else {
        const int* e32 = reinterpret_cast<const int*>(e);
        sv = reinterpret_cast<const int4*>(e32)[i];
        dv = reinterpret_cast<const int4*>(e32 + E)[i];
    }
    reinterpret_cast<int4*>(g_src)[i] = sv;
    reinterpret_cast<int4*>(g_dst)[i] = dv;
    atomicAdd(&g_deg[dv.x], 1u);
    atomicAdd(&g_deg[dv.y], 1u);
    atomicAdd(&g_deg[dv.z], 1u);
    atomicAdd(&g_deg[dv.w], 1u);
}

// Per-node: dinv, dropout1 on x, g1 = h1 * dinv
__global__ void k_node1(const float* __restrict__ x, int N, uint32_t ka, uint32_t kb) {
    int n = blockIdx.x * blockDim.x + threadIdx.x;
    if (n >= N) return;
    unsigned dg = g_deg[n];
    float dinv = dg ? rsqrtf((float)dg) : 0.0f;
    g_dinv[n] = dinv;
    float h = keep_bit(ka, kb, (uint32_t)n) ? x[n] * 2.5f : 0.0f;
    g_val[n] = h * dinv;
}

// Scalar edge scatter: agg[dst] += g_val[src].  8 edges per thread,
// gathers batched before REDs for maximum MLP.
__global__ void __launch_bounds__(256) k_edge(float* __restrict__ agg, int n8) {
    int i = blockIdx.x * blockDim.x + threadIdx.x;
    if (i >= n8) return;
    const int4* s4 = reinterpret_cast<const int4*>(g_src);
    const int4* d4 = reinterpret_cast<const int4*>(g_dst);
    int4 sa = s4[2 * i], sb = s4[2 * i + 1];
    int4 da = d4[2 * i], db = d4[2 * i + 1];
    float v0 = __ldg(&g_val[sa.x]);
    float v1 = __ldg(&g_val[sa.y]);
    float v2 = __ldg(&g_val[sa.z]);
    float v3 = __ldg(&g_val[sa.w]);
    float v4 = __ldg(&g_val[sb.x]);
    float v5 = __ldg(&g_val[sb.y]);
    float v6 = __ldg(&g_val[sb.z]);
    float v7 = __ldg(&g_val[sb.w]);
    atomicAdd(&agg[da.x], v0);
    atomicAdd(&agg[da.y], v1);
    atomicAdd(&agg[da.z], v2);
    atomicAdd(&agg[da.w], v3);
    atomicAdd(&agg[db.x], v4);
    atomicAdd(&agg[db.y], v5);
    atomicAdd(&agg[db.z], v6);
    atomicAdd(&agg[db.w], v7);
}

// Per-node: s1 = agg*dinv ; relu + dropout2 (16 ch) ; dot W2 ; g2 = t*dinv
__global__ void k_node2(const float* __restrict__ W1, const float* __restrict__ b1,
                        const float* __restrict__ W2, int N,
                        uint32_t ka, uint32_t kb) {
    int n = blockIdx.x * blockDim.x + threadIdx.x;
    if (n >= N) return;
    float dinv = g_dinv[n];
    float s1 = g_agg[n] * dinv;
    uint32_t base = (uint32_t)n * 16u;
    float t = 0.0f;
#pragma unroll
    for (int c = 0; c < 16; c++) {
        float v = fmaxf(fmaf(s1, __ldg(&W1[c]), __ldg(&b1[c])), 0.0f);
        if (keep_bit(ka, kb, base + (uint32_t)c))
            t = fmaf(v * 2.5f, __ldg(&W2[c]), t);
    }
    g_val[n] = t * dinv;
}

__global__ void k_final(float* __restrict__ out, const float* __restrict__ b2, int N) {
    int n = blockIdx.x * blockDim.x + threadIdx.x;
    if (n >= N) return;
    out[n] = out[n] * g_dinv[n] + __ldg(&b2[0]);
}

// ---------------------------------------------------------------------------
// launch
// ---------------------------------------------------------------------------
extern "C" void kernel_launch(void* const* d_in, const int* in_sizes, int n_in,
                              void* d_out, int out_size) {
    const float*     x  = (const float*)d_in[0];
    const long long* ei = (const long long*)d_in[1];
    const float*     W1 = (const float*)d_in[2];
    const float*     b1 = (const float*)d_in[3];
    const float*     W2 = (const float*)d_in[4];
    const float*     b2 = (const float*)d_in[5];
    float* out = (float*)d_out;

    int N = in_sizes[0];
    int E = in_sizes[1] / 2;

    // JAX key derivation: key(42) = (0,42); partitionable split:
    // subkey i = threefry(key, (0, i))
    uint32_t k1a, k1b, k2a, k2b;
    tf2x32(0u, 42u, 0u, 0u, k1a, k1b);
    tf2x32(0u, 42u, 0u, 1u, k2a, k2b);

    float* p_agg = nullptr;
    cudaGetSymbolAddress((void**)&p_agg, g_agg);

    const int T = 256;
    int nb = (N + T - 1) / T;
    int e4 = (E + 3) / 4;
    int cb = (e4 + T - 1) / T;
    int e8 = E / 8;
    int eb = (e8 + T - 1) / T;

    k_init   <<<nb, T>>>(out, (const unsigned*)ei, N);
    k_convert<<<cb, T>>>(ei, E);
    k_node1  <<<nb, T>>>(x, N, k1a, k1b);
    k_edge   <<<eb, T>>>(p_agg, e8);
    k_node2  <<<nb, T>>>(W1, b1, W2, N, k2a, k2b);
    k_edge   <<<eb, T>>>(out, e8);
    k_final  <<<nb, T>>>(out, b2, N);
}

// round 6
// speedup vs baseline: 1.1822x; 1.1822x over previous
#include <cuda_runtime.h>
#include <cuda_fp16.h>
#include <stdint.h>

#define N_MAX 100000
#define E_MAX 6400000

// ---- scratch (device globals: no allocation allowed) ----
__device__ int      g_src[E_MAX];
__device__ int      g_dst[E_MAX];
__device__ unsigned g_deg[N_MAX];
__device__ float    g_dinv[N_MAX];
__device__ __half   g_val[N_MAX];   // per-node payload — fp16 so the 200KB table is ~L1-resident
__device__ float    g_agg[N_MAX];   // layer-1 aggregation (fp32 atomics)
__device__ int      g_is64;         // edge_index dtype flag (1 = int64)

// ---------------------------------------------------------------------------
// threefry2x32 — exact JAX schedule: 20 rounds = 5 blocks of 4
// ---------------------------------------------------------------------------
__host__ __device__ __forceinline__ void tf2x32(uint32_t k0, uint32_t k1,
                                                uint32_t x0, uint32_t x1,
                                                uint32_t &o0, uint32_t &o1) {
    const uint32_t ks2 = k0 ^ k1 ^ 0x1BD11BDAu;
#define TF_RND(R) { x0 += x1; x1 = (x1 << (R)) | (x1 >> (32 - (R))); x1 ^= x0; }
    x0 += k0; x1 += k1;
    TF_RND(13) TF_RND(15) TF_RND(26) TF_RND(6)
    x0 += k1;  x1 += ks2 + 1u;
    TF_RND(17) TF_RND(29) TF_RND(16) TF_RND(24)
    x0 += ks2; x1 += k0 + 2u;
    TF_RND(13) TF_RND(15) TF_RND(26) TF_RND(6)
    x0 += k0;  x1 += k1 + 3u;
    TF_RND(17) TF_RND(29) TF_RND(16) TF_RND(24)
    x0 += k1;  x1 += ks2 + 4u;
    TF_RND(13) TF_RND(15) TF_RND(26) TF_RND(6)
    x0 += ks2; x1 += k0 + 5u;
#undef TF_RND
    o0 = x0; o1 = x1;
}

__device__ __forceinline__ bool keep_bit(uint32_t ka, uint32_t kb, uint32_t idx) {
    uint32_t a, b;
    tf2x32(ka, kb, 0u, idx, a, b);
    uint32_t bits = a ^ b;
    float u = __uint_as_float((bits >> 9) | 0x3f800000u) - 1.0f;
    return u < 0.4f;
}

// ---------------------------------------------------------------------------
// kernels
// ---------------------------------------------------------------------------

// zero counters/accumulators/out + dtype detection (block 0)
__global__ void k_init(float* __restrict__ out, const unsigned* __restrict__ e, int N) {
    int n = blockIdx.x * blockDim.x + threadIdx.x;
    if (n < N) { g_deg[n] = 0u; g_agg[n] = 0.0f; out[n] = 0.0f; }
    if (blockIdx.x == 0) {
        __shared__ int any32;
        if (threadIdx.x == 0) any32 = 0;
        __syncthreads();
        int local = 0;
        for (int j = threadIdx.x; j < 4096; j += blockDim.x)
            if (e[2 * j + 1] != 0u) local = 1;
        if (local) any32 = 1;
        __syncthreads();
        if (threadIdx.x == 0) g_is64 = (any32 == 0) ? 1 : 0;
    }
}

// Convert edge_index -> int32 src/dst and count in-degree. 4 edges per thread.
__global__ void __launch_bounds__(256) k_convert(const long long* __restrict__ e, int E) {
    int i = blockIdx.x * blockDim.x + threadIdx.x;   // quad index
    if (i * 4 >= E) return;
    int4 sv, dv;
    if (g_is64) {
        const longlong2* s2 = reinterpret_cast<const longlong2*>(e);
        const longlong2* d2 = reinterpret_cast<const longlong2*>(e + E);
        longlong2 sa = s2[2 * i], sb = s2[2 * i + 1];
        longlong2 da = d2[2 * i], db = d2[2 * i + 1];
        sv = make_int4((int)sa.x, (int)sa.y, (int)sb.x, (int)sb.y);
        dv = make_int4((int)da.x, (int)da.y, (int)db.x, (int)db.y);
    } else {
        const int* e32 = reinterpret_cast<const int*>(e);
        sv = reinterpret_cast<const int4*>(e32)[i];
        dv = reinterpret_cast<const int4*>(e32 + E)[i];
    }
    reinterpret_cast<int4*>(g_src)[i] = sv;
    reinterpret_cast<int4*>(g_dst)[i] = dv;
    atomicAdd(&g_deg[dv.x], 1u);
    atomicAdd(&g_deg[dv.y], 1u);
    atomicAdd(&g_deg[dv.z], 1u);
    atomicAdd(&g_deg[dv.w], 1u);
}

// Per-node: dinv, dropout1 on x, g1 = h1 * dinv  (stored fp16)
__global__ void k_node1(const float* __restrict__ x, int N, uint32_t ka, uint32_t kb) {
    int n = blockIdx.x * blockDim.x + threadIdx.x;
    if (n >= N) return;
    unsigned dg = g_deg[n];
    float dinv = dg ? rsqrtf((float)dg) : 0.0f;
    g_dinv[n] = dinv;
    float h = keep_bit(ka, kb, (uint32_t)n) ? x[n] * 2.5f : 0.0f;
    g_val[n] = __float2half_rn(h * dinv);
}

// Scalar edge scatter: agg[dst] += g_val[src].  4 edges per thread,
// gathers (fp16, mostly L1 hits) batched before the fp32 REDs.
__global__ void __launch_bounds__(256) k_edge(float* __restrict__ agg, int n4) {
    int i = blockIdx.x * blockDim.x + threadIdx.x;
    if (i >= n4) return;
    int4 s = reinterpret_cast<const int4*>(g_src)[i];
    int4 d = reinterpret_cast<const int4*>(g_dst)[i];
    float v0 = __half2float(__ldg(&g_val[s.x]));
    float v1 = __half2float(__ldg(&g_val[s.y]));
    float v2 = __half2float(__ldg(&g_val[s.z]));
    float v3 = __half2float(__ldg(&g_val[s.w]));
    atomicAdd(&agg[d.x], v0);
    atomicAdd(&agg[d.y], v1);
    atomicAdd(&agg[d.z], v2);
    atomicAdd(&agg[d.w], v3);
}

// Per-node: s1 = agg*dinv ; relu + dropout2 (16 ch) ; dot W2 ; g2 = t*dinv (fp16)
__global__ void k_node2(const float* __restrict__ W1, const float* __restrict__ b1,
                        const float* __restrict__ W2, int N,
                        uint32_t ka, uint32_t kb) {
    int n = blockIdx.x * blockDim.x + threadIdx.x;
    if (n >= N) return;
    float dinv = g_dinv[n];
    float s1 = g_agg[n] * dinv;
    uint32_t base = (uint32_t)n * 16u;
    float t = 0.0f;
#pragma unroll
    for (int c = 0; c < 16; c++) {
        float v = fmaxf(fmaf(s1, __ldg(&W1[c]), __ldg(&b1[c])), 0.0f);
        if (keep_bit(ka, kb, base + (uint32_t)c))
            t = fmaf(v * 2.5f, __ldg(&W2[c]), t);
    }
    g_val[n] = __float2half_rn(t * dinv);
}

__global__ void k_final(float* __restrict__ out, const float* __restrict__ b2, int N) {
    int n = blockIdx.x * blockDim.x + threadIdx.x;
    if (n >= N) return;
    out[n] = out[n] * g_dinv[n] + __ldg(&b2[0]);
}

// ---------------------------------------------------------------------------
// launch
// ---------------------------------------------------------------------------
extern "C" void kernel_launch(void* const* d_in, const int* in_sizes, int n_in,
                              void* d_out, int out_size) {
    const float*     x  = (const float*)d_in[0];
    const long long* ei = (const long long*)d_in[1];
    const float*     W1 = (const float*)d_in[2];
    const float*     b1 = (const float*)d_in[3];
    const float*     W2 = (const float*)d_in[4];
    const float*     b2 = (const float*)d_in[5];
    float* out = (float*)d_out;

    int N = in_sizes[0];
    int E = in_sizes[1] / 2;

    // JAX key derivation: key(42) = (0,42); partitionable split:
    // subkey i = threefry(key, (0, i))
    uint32_t k1a, k1b, k2a, k2b;
    tf2x32(0u, 42u, 0u, 0u, k1a, k1b);
    tf2x32(0u, 42u, 0u, 1u, k2a, k2b);

    float* p_agg = nullptr;
    cudaGetSymbolAddress((void**)&p_agg, g_agg);

    const int T = 256;
    int nb = (N + T - 1) / T;
    int e4 = (E + 3) / 4;
    int cb = (e4 + T - 1) / T;
    int eb = (e4 + T - 1) / T;

    k_init   <<<nb, T>>>(out, (const unsigned*)ei, N);
    k_convert<<<cb, T>>>(ei, E);
    k_node1  <<<nb, T>>>(x, N, k1a, k1b);
    k_edge   <<<eb, T>>>(p_agg, e4);
    k_node2  <<<nb, T>>>(W1, b1, W2, N, k2a, k2b);
    k_edge   <<<eb, T>>>(out, e4);
    k_final  <<<nb, T>>>(out, b2, N);
}